// round 1
// baseline (speedup 1.0000x reference)
#include <cuda_runtime.h>

#define N     8192
#define OBS   64
#define ACT   16
#define ITERS 64

#define ROWS_PER_BLOCK 8          // 8 warps/block, warp-per-row
#define FIRST_ROW (OBS + 1)       // rows 0..64 of intermediate outputs are discarded

// Ping-pong hidden-state buffers (device globals: no allocation allowed).
__device__ float g_hA[N];
__device__ float g_hB[N];

// Initialize: slots 0..64 = [1, obs] in BOTH buffers (constant across iters),
// slots 65.. of A from rnn_state.
__global__ void init_kernel(const float* __restrict__ obs,
                            const float* __restrict__ h0) {
    int i = blockIdx.x * blockDim.x + threadIdx.x;
    if (i >= N) return;
    if (i == 0) {
        g_hA[0] = 1.0f;
        g_hB[0] = 1.0f;
    } else if (i <= OBS) {
        float v = obs[i - 1];
        g_hA[i] = v;
        g_hB[i] = v;
    } else {
        g_hA[i] = h0[i];
    }
}

// One RNN step: hout[row] = tanh(W[row,:] . hin) for row in [65, N).
// srcA=1 : read g_hA, write g_hB ; srcA=0 : read g_hB, write g_hA.
__global__ __launch_bounds__(32 * ROWS_PER_BLOCK)
void gemv_tanh_kernel(const float4* __restrict__ W, int srcA) {
    const float4* __restrict__ hin =
        (const float4*)(srcA ? (const float*)g_hA : (const float*)g_hB);
    float* __restrict__ hout = srcA ? g_hB : g_hA;

    const int warp = threadIdx.x >> 5;
    const int lane = threadIdx.x & 31;
    const int row  = FIRST_ROW + blockIdx.x * ROWS_PER_BLOCK + warp;
    if (row >= N) return;

    const float4* __restrict__ wr = W + (size_t)row * (N / 4);

    float acc = 0.0f;
#pragma unroll 8
    for (int i = 0; i < (N / 4) / 32; ++i) {        // 64 iterations
        float4 w = wr[i * 32 + lane];
        float4 h = __ldg(&hin[i * 32 + lane]);
        acc += w.x * h.x + w.y * h.y + w.z * h.z + w.w * h.w;
    }
#pragma unroll
    for (int off = 16; off; off >>= 1)
        acc += __shfl_down_sync(0xffffffffu, acc, off);
    if (lane == 0)
        hout[row] = tanhf(acc);
}

// Final step: only the last ACT rows are needed; write straight to d_out.
__global__ __launch_bounds__(32 * ACT)
void gemv_tail_kernel(const float4* __restrict__ W, int srcA,
                      float* __restrict__ out) {
    const float4* __restrict__ hin =
        (const float4*)(srcA ? (const float*)g_hA : (const float*)g_hB);

    const int warp = threadIdx.x >> 5;   // 0..15
    const int lane = threadIdx.x & 31;
    const int row  = (N - ACT) + warp;

    const float4* __restrict__ wr = W + (size_t)row * (N / 4);

    float acc = 0.0f;
#pragma unroll 8
    for (int i = 0; i < (N / 4) / 32; ++i) {
        float4 w = wr[i * 32 + lane];
        float4 h = __ldg(&hin[i * 32 + lane]);
        acc += w.x * h.x + w.y * h.y + w.z * h.z + w.w * h.w;
    }
#pragma unroll
    for (int off = 16; off; off >>= 1)
        acc += __shfl_down_sync(0xffffffffu, acc, off);
    if (lane == 0)
        out[warp] = tanhf(acc);
}

extern "C" void kernel_launch(void* const* d_in, const int* in_sizes, int n_in,
                              void* d_out, int out_size) {
    const float* W   = (const float*)d_in[0];  // [N, N] fp32, row-major
    const float* obs = (const float*)d_in[1];  // [OBS]
    const float* h0  = (const float*)d_in[2];  // [N]
    float* out = (float*)d_out;                // [ACT]

    init_kernel<<<(N + 255) / 256, 256>>>(obs, h0);

    const int rows   = N - FIRST_ROW;                          // 8127
    const int blocks = (rows + ROWS_PER_BLOCK - 1) / ROWS_PER_BLOCK;

    int srcA = 1;
    for (int it = 0; it < ITERS - 1; ++it) {                   // 63 full steps
        gemv_tanh_kernel<<<blocks, 32 * ROWS_PER_BLOCK>>>((const float4*)W, srcA);
        srcA ^= 1;
    }
    gemv_tail_kernel<<<1, 32 * ACT>>>((const float4*)W, srcA, out);  // step 64
}